// round 2
// baseline (speedup 1.0000x reference)
#include <cuda_runtime.h>
#include <math.h>

#define CH   512
#define SP   3136
#define NB   32
#define MTOT 100352
#define EPSV 1e-5f

typedef unsigned long long ull;

// packed fp32x2 FMA (sm_100+): 2 MACs per instruction, full fp32 precision
__device__ __forceinline__ ull ffma2(ull a, ull b, ull c) {
    ull d;
    asm("fma.rn.f32x2 %0, %1, %2, %3;" : "=l"(d) : "l"(a), "l"(b), "l"(c));
    return d;
}
__device__ __forceinline__ float2 u2f2(ull v) {
    float2 r;
    asm("mov.b64 {%0, %1}, %2;" : "=f"(r.x), "=f"(r.y) : "l"(v));
    return r;
}

// ---------------- scratch (device globals; no allocation allowed) ------------
__device__ float g_meanpart[NB * CH];
__device__ float g_mean[CH];
__device__ float g_Gpart[(size_t)NB * CH * CH];   // 33.5 MB partial Gram
__device__ float g_Sigma[CH * CH];
__device__ float g_SigmaN[CH * CH];
__device__ float g_Pa[CH * CH];
__device__ float g_Pb[CH * CH];
__device__ float g_P2[CH * CH];
__device__ float g_PS[CH * CH];
__device__ float g_M[CH * CH];
__device__ float g_bias[CH];
__device__ float g_scal[2];   // [0] = 1/tr(Sigma), [1] = sqrt(1/tr)

// ---------------- mean ------------------------------------------------------
__global__ void k_mean_part(const float* __restrict__ X) {
    const int c = blockIdx.x, b = blockIdx.y;
    const float* p = X + ((size_t)b * CH + c) * SP;
    float s = 0.f;
    for (int i = threadIdx.x; i < SP; i += 256) s += p[i];
    __shared__ float red[256];
    red[threadIdx.x] = s;
    __syncthreads();
    for (int o = 128; o > 0; o >>= 1) {
        if (threadIdx.x < o) red[threadIdx.x] += red[threadIdx.x + o];
        __syncthreads();
    }
    if (threadIdx.x == 0) g_meanpart[b * CH + c] = red[0];
}

__global__ void k_mean_final() {
    const int c = blockIdx.x * 256 + threadIdx.x;
    float s = 0.f;
    #pragma unroll
    for (int b = 0; b < NB; b++) s += g_meanpart[b * CH + c];
    g_mean[c] = s * (1.0f / MTOT);
}

// ---------------- Gram: Gpart[b] = X_b @ X_b^T (128x128 tiles, f32x2) -------
__global__ void __launch_bounds__(256) k_gram(const float* __restrict__ X) {
    const int b  = blockIdx.z;
    const int i0 = blockIdx.x * 128;
    const int j0 = blockIdx.y * 128;
    const float* Xb = X + (size_t)b * CH * SP;

    __shared__ float As[8][256];   // duplicated pairs: As[k][2i]=As[k][2i+1]
    __shared__ float Bs[8][128];

    const int tid = threadIdx.x;
    const int tx = tid & 15, ty = tid >> 4;

    ull acc[8][4];
    #pragma unroll
    for (int r = 0; r < 8; r++)
        #pragma unroll
        for (int c = 0; c < 4; c++) acc[r][c] = 0ull;

    const int lr = tid >> 1;          // 0..127
    const int lq = (tid & 1) * 4;     // 0 or 4
    const float* pa = Xb + (size_t)(i0 + lr) * SP + lq;
    const float* pb = Xb + (size_t)(j0 + lr) * SP + lq;

    for (int k0 = 0; k0 < SP; k0 += 8) {
        float4 av = *(const float4*)(pa + k0);
        float4 bv = *(const float4*)(pb + k0);
        __syncthreads();
        As[lq + 0][2 * lr] = av.x; As[lq + 0][2 * lr + 1] = av.x;
        As[lq + 1][2 * lr] = av.y; As[lq + 1][2 * lr + 1] = av.y;
        As[lq + 2][2 * lr] = av.z; As[lq + 2][2 * lr + 1] = av.z;
        As[lq + 3][2 * lr] = av.w; As[lq + 3][2 * lr + 1] = av.w;
        Bs[lq + 0][lr] = bv.x;
        Bs[lq + 1][lr] = bv.y;
        Bs[lq + 2][lr] = bv.z;
        Bs[lq + 3][lr] = bv.w;
        __syncthreads();
        #pragma unroll
        for (int kk = 0; kk < 8; kk++) {
            const ull* ap = (const ull*)&As[kk][ty * 16];
            const ull* bp = (const ull*)&Bs[kk][tx * 8];
            ull a[8], bb[4];
            #pragma unroll
            for (int r = 0; r < 8; r++) a[r] = ap[r];
            #pragma unroll
            for (int c = 0; c < 4; c++) bb[c] = bp[c];
            #pragma unroll
            for (int r = 0; r < 8; r++)
                #pragma unroll
                for (int c = 0; c < 4; c++)
                    acc[r][c] = ffma2(a[r], bb[c], acc[r][c]);
        }
    }

    float* Gp = g_Gpart + (size_t)b * CH * CH;
    #pragma unroll
    for (int r = 0; r < 8; r++) {
        const int gi = i0 + ty * 8 + r;
        float* row = Gp + (size_t)gi * CH + j0 + tx * 8;
        #pragma unroll
        for (int c = 0; c < 4; c++) {
            float2 v = u2f2(acc[r][c]);
            row[2 * c] = v.x;
            row[2 * c + 1] = v.y;
        }
    }
}

// ---------------- Sigma = G/m - mu mu^T + eps I -----------------------------
__global__ void k_sigma() {
    const int idx = blockIdx.x * 256 + threadIdx.x;
    float s = 0.f;
    #pragma unroll 8
    for (int p = 0; p < NB; p++) s += g_Gpart[(size_t)p * CH * CH + idx];
    const int i = idx >> 9, j = idx & 511;
    float v = s * (1.0f / MTOT) - g_mean[i] * g_mean[j];
    if (i == j) v += EPSV;
    g_Sigma[idx] = v;
}

__global__ void k_trace() {
    __shared__ float red[512];
    const int t = threadIdx.x;
    red[t] = g_Sigma[t * (CH + 1)];
    __syncthreads();
    for (int o = 256; o > 0; o >>= 1) {
        if (t < o) red[t] += red[t + o];
        __syncthreads();
    }
    if (t == 0) {
        float inv = 1.0f / red[0];
        g_scal[0] = inv;
        g_scal[1] = sqrtf(inv);
    }
}

__global__ void k_prep() {
    const int idx = blockIdx.x * 256 + threadIdx.x;
    g_SigmaN[idx] = g_Sigma[idx] * g_scal[0];
    const int i = idx >> 9, j = idx & 511;
    g_Pa[idx] = (i == j) ? 1.0f : 0.0f;
}

// ---------------- 512^3 matmul core (64x64 tiles, f32x2) --------------------
__device__ __forceinline__ void mm512_acc(const float* __restrict__ A,
                                          const float* __restrict__ B,
                                          int i0, int j0, ull acc[4][2]) {
    __shared__ float As[16][128];   // duplicated pairs
    __shared__ float Bs[16][64];
    const int tid = threadIdx.x;
    const int tx = tid & 15, ty = tid >> 4;
    #pragma unroll
    for (int r = 0; r < 4; r++)
        #pragma unroll
        for (int c = 0; c < 2; c++) acc[r][c] = 0ull;

    const int lr = tid >> 2;          // 0..63 (A row)
    const int lq = (tid & 3) * 4;     // 0,4,8,12 (A k)
    const int kb = tid >> 4;          // 0..15 (B k row)
    const int jb = (tid & 15) * 4;    // B col

    for (int k0 = 0; k0 < 512; k0 += 16) {
        float4 av = *(const float4*)(A + (size_t)(i0 + lr) * 512 + k0 + lq);
        float4 bv = *(const float4*)(B + (size_t)(k0 + kb) * 512 + j0 + jb);
        __syncthreads();
        As[lq + 0][2 * lr] = av.x; As[lq + 0][2 * lr + 1] = av.x;
        As[lq + 1][2 * lr] = av.y; As[lq + 1][2 * lr + 1] = av.y;
        As[lq + 2][2 * lr] = av.z; As[lq + 2][2 * lr + 1] = av.z;
        As[lq + 3][2 * lr] = av.w; As[lq + 3][2 * lr + 1] = av.w;
        *(float4*)&Bs[kb][jb] = bv;
        __syncthreads();
        #pragma unroll
        for (int kk = 0; kk < 16; kk++) {
            const ull* ap = (const ull*)&As[kk][ty * 8];
            const ull* bp = (const ull*)&Bs[kk][tx * 4];
            ull a[4], bb[2];
            #pragma unroll
            for (int r = 0; r < 4; r++) a[r] = ap[r];
            bb[0] = bp[0]; bb[1] = bp[1];
            #pragma unroll
            for (int r = 0; r < 4; r++) {
                acc[r][0] = ffma2(a[r], bb[0], acc[r][0]);
                acc[r][1] = ffma2(a[r], bb[1], acc[r][1]);
            }
        }
    }
}

// dual: z=0: P2 = P@P ; z=1: PS = P@SigmaN (one launch, runs concurrently)
__global__ void __launch_bounds__(256) k_ns_dual(int pb) {
    const float* P  = pb ? g_Pb : g_Pa;
    const float* Bm = blockIdx.z ? g_SigmaN : P;
    float*       Cm = blockIdx.z ? g_PS : g_P2;
    const int i0 = blockIdx.y * 64, j0 = blockIdx.x * 64;
    ull acc[4][2];
    mm512_acc(P, Bm, i0, j0, acc);
    const int tx = threadIdx.x & 15, ty = threadIdx.x >> 4;
    #pragma unroll
    for (int r = 0; r < 4; r++) {
        float* row = Cm + (size_t)(i0 + ty * 4 + r) * 512 + j0 + tx * 4;
        float2 v0 = u2f2(acc[r][0]), v1 = u2f2(acc[r][1]);
        row[0] = v0.x; row[1] = v0.y; row[2] = v1.x; row[3] = v1.y;
    }
}

// Pnext = 1.5*P - 0.5*(P2 @ PS)
__global__ void __launch_bounds__(256) k_ns_combine(int pb) {
    const float* Pc = pb ? g_Pb : g_Pa;
    float*       Pn = pb ? g_Pa : g_Pb;
    const int i0 = blockIdx.y * 64, j0 = blockIdx.x * 64;
    ull acc[4][2];
    mm512_acc(g_P2, g_PS, i0, j0, acc);
    const int tx = threadIdx.x & 15, ty = threadIdx.x >> 4;
    #pragma unroll
    for (int r = 0; r < 4; r++) {
        const size_t base = (size_t)(i0 + ty * 4 + r) * 512 + j0 + tx * 4;
        float2 v0 = u2f2(acc[r][0]), v1 = u2f2(acc[r][1]);
        Pn[base + 0] = 1.5f * Pc[base + 0] - 0.5f * v0.x;
        Pn[base + 1] = 1.5f * Pc[base + 1] - 0.5f * v0.y;
        Pn[base + 2] = 1.5f * Pc[base + 2] - 0.5f * v1.x;
        Pn[base + 3] = 1.5f * Pc[base + 3] - 0.5f * v1.y;
    }
}

// M = rot @ P_final * sqrt(1/tr)
__global__ void __launch_bounds__(256) k_rotP(const float* __restrict__ rot, int pb) {
    const float* Pf = pb ? g_Pb : g_Pa;
    const int i0 = blockIdx.y * 64, j0 = blockIdx.x * 64;
    ull acc[4][2];
    mm512_acc(rot, Pf, i0, j0, acc);
    const float s = g_scal[1];
    const int tx = threadIdx.x & 15, ty = threadIdx.x >> 4;
    #pragma unroll
    for (int r = 0; r < 4; r++) {
        float* row = g_M + (size_t)(i0 + ty * 4 + r) * 512 + j0 + tx * 4;
        float2 v0 = u2f2(acc[r][0]), v1 = u2f2(acc[r][1]);
        row[0] = v0.x * s; row[1] = v0.y * s; row[2] = v1.x * s; row[3] = v1.y * s;
    }
}

__global__ void k_bias() {
    const int i = blockIdx.x * 256 + threadIdx.x;
    float s = 0.f;
    #pragma unroll 8
    for (int c = 0; c < CH; c++) s += g_M[(size_t)i * CH + c] * g_mean[c];
    g_bias[i] = s;
}

// ---------------- out[b] = M @ X_b - bias (128x128 tiles) -------------------
__global__ void __launch_bounds__(256) k_out(const float* __restrict__ X,
                                             float* __restrict__ out) {
    const int b  = blockIdx.z;
    const int i0 = blockIdx.y * 128;
    const int s0 = blockIdx.x * 128;
    const float* Xb = X + (size_t)b * CH * SP;
    float* Ob = out + (size_t)b * CH * SP;

    __shared__ float As[8][256];
    __shared__ float Bs[8][128];

    const int tid = threadIdx.x;
    const int tx = tid & 15, ty = tid >> 4;

    ull acc[8][4];
    #pragma unroll
    for (int r = 0; r < 8; r++)
        #pragma unroll
        for (int c = 0; c < 4; c++) acc[r][c] = 0ull;

    const int lr = tid >> 1;          // M row 0..127
    const int lq = (tid & 1) * 4;     // M k 0/4
    const int kb = tid >> 5;          // X k row 0..7
    const int sb = (tid & 31) * 4;    // X col

    const bool bvalid = (s0 + sb) < SP;

    for (int k0 = 0; k0 < CH; k0 += 8) {
        float4 av = *(const float4*)(g_M + (size_t)(i0 + lr) * CH + k0 + lq);
        float4 bv = make_float4(0.f, 0.f, 0.f, 0.f);
        if (bvalid) bv = *(const float4*)(Xb + (size_t)(k0 + kb) * SP + s0 + sb);
        __syncthreads();
        As[lq + 0][2 * lr] = av.x; As[lq + 0][2 * lr + 1] = av.x;
        As[lq + 1][2 * lr] = av.y; As[lq + 1][2 * lr + 1] = av.y;
        As[lq + 2][2 * lr] = av.z; As[lq + 2][2 * lr + 1] = av.z;
        As[lq + 3][2 * lr] = av.w; As[lq + 3][2 * lr + 1] = av.w;
        *(float4*)&Bs[kb][sb] = bv;
        __syncthreads();
        #pragma unroll
        for (int kk = 0; kk < 8; kk++) {
            const ull* ap = (const ull*)&As[kk][ty * 16];
            const ull* bp = (const ull*)&Bs[kk][tx * 8];
            ull a[8], bb[4];
            #pragma unroll
            for (int r = 0; r < 8; r++) a[r] = ap[r];
            #pragma unroll
            for (int c = 0; c < 4; c++) bb[c] = bp[c];
            #pragma unroll
            for (int r = 0; r < 8; r++)
                #pragma unroll
                for (int c = 0; c < 4; c++)
                    acc[r][c] = ffma2(a[r], bb[c], acc[r][c]);
        }
    }

    const int sj = s0 + tx * 8;
    if (sj < SP) {
        #pragma unroll
        for (int r = 0; r < 8; r++) {
            const int gi = i0 + ty * 8 + r;
            const float bi = g_bias[gi];
            float* row = Ob + (size_t)gi * SP + sj;
            #pragma unroll
            for (int c = 0; c < 4; c++) {
                float2 v = u2f2(acc[r][c]);
                row[2 * c]     = v.x - bi;
                row[2 * c + 1] = v.y - bi;
            }
        }
    }
}

// ---------------- launch ----------------------------------------------------
extern "C" void kernel_launch(void* const* d_in, const int* in_sizes, int n_in,
                              void* d_out, int out_size) {
    const float* X   = (const float*)d_in[0];
    const float* rot = (const float*)d_in[1];
    float* out = (float*)d_out;
    (void)in_sizes; (void)n_in; (void)out_size;

    k_mean_part<<<dim3(CH, NB), 256>>>(X);
    k_mean_final<<<2, 256>>>();

    k_gram<<<dim3(4, 4, NB), 256>>>(X);
    k_sigma<<<1024, 256>>>();
    k_trace<<<1, 512>>>();
    k_prep<<<1024, 256>>>();

    // 10 Newton-Schulz iterations (T=10 fixed by setup_inputs)
    for (int t = 0; t < 10; t++) {
        const int pb = t & 1;                   // which buffer holds P_t
        k_ns_dual<<<dim3(8, 8, 2), 256>>>(pb);  // P2 = P@P, PS = P@SigmaN
        k_ns_combine<<<dim3(8, 8), 256>>>(pb);  // P_{t+1} = 1.5P - 0.5*P2@PS
    }
    // after 10 iters, P_final sits in g_Pa (even count)
    k_rotP<<<dim3(8, 8), 256>>>(rot, 0);
    k_bias<<<2, 256>>>();

    k_out<<<dim3(25, 4, NB), 256>>>(X, out);
}

// round 3
// speedup vs baseline: 1.0005x; 1.0005x over previous
#include <cuda_runtime.h>
#include <math.h>

#define CH   512
#define SP   3136
#define NB   32
#define MTOT 100352
#define EPSV 1e-5f

typedef unsigned long long ull;

// packed fp32x2 FMA (sm_100+): 2 MACs per instruction, full fp32 precision
__device__ __forceinline__ ull ffma2(ull a, ull b, ull c) {
    ull d;
    asm("fma.rn.f32x2 %0, %1, %2, %3;" : "=l"(d) : "l"(a), "l"(b), "l"(c));
    return d;
}
__device__ __forceinline__ float2 u2f2(ull v) {
    float2 r;
    asm("mov.b64 {%0, %1}, %2;" : "=f"(r.x), "=f"(r.y) : "l"(v));
    return r;
}

// ---------------- scratch (device globals; no allocation allowed) ------------
__device__ float g_meanpart[NB * CH];
__device__ float g_mean[CH];
__device__ float g_Gpart[(size_t)NB * CH * CH];   // 33.5 MB partial Gram
__device__ float g_Sigma[CH * CH];
__device__ float g_SigmaN[CH * CH];
__device__ float g_Pa[CH * CH];
__device__ float g_Pb[CH * CH];
__device__ float g_P2[CH * CH];
__device__ float g_PS[CH * CH];
__device__ float g_M[CH * CH];
__device__ float g_bias[CH];
__device__ float g_scal[2];   // [0] = 1/tr(Sigma), [1] = sqrt(1/tr)

// ---------------- mean ------------------------------------------------------
__global__ void k_mean_part(const float* __restrict__ X) {
    const int c = blockIdx.x, b = blockIdx.y;
    const float* p = X + ((size_t)b * CH + c) * SP;
    float s = 0.f;
    for (int i = threadIdx.x; i < SP; i += 256) s += p[i];
    __shared__ float red[256];
    red[threadIdx.x] = s;
    __syncthreads();
    for (int o = 128; o > 0; o >>= 1) {
        if (threadIdx.x < o) red[threadIdx.x] += red[threadIdx.x + o];
        __syncthreads();
    }
    if (threadIdx.x == 0) g_meanpart[b * CH + c] = red[0];
}

__global__ void k_mean_final() {
    const int c = blockIdx.x * 256 + threadIdx.x;
    float s = 0.f;
    #pragma unroll
    for (int b = 0; b < NB; b++) s += g_meanpart[b * CH + c];
    g_mean[c] = s * (1.0f / MTOT);
}

// ---------------- Gram: Gpart[b] = X_b @ X_b^T (128x128 tiles, f32x2) -------
__global__ void __launch_bounds__(256) k_gram(const float* __restrict__ X) {
    const int b  = blockIdx.z;
    const int i0 = blockIdx.x * 128;
    const int j0 = blockIdx.y * 128;
    const float* Xb = X + (size_t)b * CH * SP;

    __shared__ float As[8][256];   // duplicated pairs: As[k][2i]=As[k][2i+1]
    __shared__ float Bs[8][128];

    const int tid = threadIdx.x;
    const int tx = tid & 15, ty = tid >> 4;

    ull acc[8][4];
    #pragma unroll
    for (int r = 0; r < 8; r++)
        #pragma unroll
        for (int c = 0; c < 4; c++) acc[r][c] = 0ull;

    const int lr = tid >> 1;          // 0..127
    const int lq = (tid & 1) * 4;     // 0 or 4
    const float* pa = Xb + (size_t)(i0 + lr) * SP + lq;
    const float* pb = Xb + (size_t)(j0 + lr) * SP + lq;

    for (int k0 = 0; k0 < SP; k0 += 8) {
        float4 av = *(const float4*)(pa + k0);
        float4 bv = *(const float4*)(pb + k0);
        __syncthreads();
        As[lq + 0][2 * lr] = av.x; As[lq + 0][2 * lr + 1] = av.x;
        As[lq + 1][2 * lr] = av.y; As[lq + 1][2 * lr + 1] = av.y;
        As[lq + 2][2 * lr] = av.z; As[lq + 2][2 * lr + 1] = av.z;
        As[lq + 3][2 * lr] = av.w; As[lq + 3][2 * lr + 1] = av.w;
        Bs[lq + 0][lr] = bv.x;
        Bs[lq + 1][lr] = bv.y;
        Bs[lq + 2][lr] = bv.z;
        Bs[lq + 3][lr] = bv.w;
        __syncthreads();
        #pragma unroll
        for (int kk = 0; kk < 8; kk++) {
            const ull* ap = (const ull*)&As[kk][ty * 16];
            const ull* bp = (const ull*)&Bs[kk][tx * 8];
            ull a[8], bb[4];
            #pragma unroll
            for (int r = 0; r < 8; r++) a[r] = ap[r];
            #pragma unroll
            for (int c = 0; c < 4; c++) bb[c] = bp[c];
            #pragma unroll
            for (int r = 0; r < 8; r++)
                #pragma unroll
                for (int c = 0; c < 4; c++)
                    acc[r][c] = ffma2(a[r], bb[c], acc[r][c]);
        }
    }

    float* Gp = g_Gpart + (size_t)b * CH * CH;
    #pragma unroll
    for (int r = 0; r < 8; r++) {
        const int gi = i0 + ty * 8 + r;
        float* row = Gp + (size_t)gi * CH + j0 + tx * 8;
        #pragma unroll
        for (int c = 0; c < 4; c++) {
            float2 v = u2f2(acc[r][c]);
            row[2 * c] = v.x;
            row[2 * c + 1] = v.y;
        }
    }
}

// ---------------- Sigma = G/m - mu mu^T + eps I -----------------------------
__global__ void k_sigma() {
    const int idx = blockIdx.x * 256 + threadIdx.x;
    float s = 0.f;
    #pragma unroll 8
    for (int p = 0; p < NB; p++) s += g_Gpart[(size_t)p * CH * CH + idx];
    const int i = idx >> 9, j = idx & 511;
    float v = s * (1.0f / MTOT) - g_mean[i] * g_mean[j];
    if (i == j) v += EPSV;
    g_Sigma[idx] = v;
}

__global__ void k_trace() {
    __shared__ float red[512];
    const int t = threadIdx.x;
    red[t] = g_Sigma[t * (CH + 1)];
    __syncthreads();
    for (int o = 256; o > 0; o >>= 1) {
        if (t < o) red[t] += red[t + o];
        __syncthreads();
    }
    if (t == 0) {
        float inv = 1.0f / red[0];
        g_scal[0] = inv;
        g_scal[1] = sqrtf(inv);
    }
}

__global__ void k_prep() {
    const int idx = blockIdx.x * 256 + threadIdx.x;
    g_SigmaN[idx] = g_Sigma[idx] * g_scal[0];
    const int i = idx >> 9, j = idx & 511;
    g_Pa[idx] = (i == j) ? 1.0f : 0.0f;
}

// ---------------- 512^3 matmul core (64x64 tiles, f32x2) --------------------
__device__ __forceinline__ void mm512_acc(const float* __restrict__ A,
                                          const float* __restrict__ B,
                                          int i0, int j0, ull acc[4][2]) {
    __shared__ float As[16][128];   // duplicated pairs
    __shared__ float Bs[16][64];
    const int tid = threadIdx.x;
    const int tx = tid & 15, ty = tid >> 4;
    #pragma unroll
    for (int r = 0; r < 4; r++)
        #pragma unroll
        for (int c = 0; c < 2; c++) acc[r][c] = 0ull;

    const int lr = tid >> 2;          // 0..63 (A row)
    const int lq = (tid & 3) * 4;     // 0,4,8,12 (A k)
    const int kb = tid >> 4;          // 0..15 (B k row)
    const int jb = (tid & 15) * 4;    // B col

    for (int k0 = 0; k0 < 512; k0 += 16) {
        float4 av = *(const float4*)(A + (size_t)(i0 + lr) * 512 + k0 + lq);
        float4 bv = *(const float4*)(B + (size_t)(k0 + kb) * 512 + j0 + jb);
        __syncthreads();
        As[lq + 0][2 * lr] = av.x; As[lq + 0][2 * lr + 1] = av.x;
        As[lq + 1][2 * lr] = av.y; As[lq + 1][2 * lr + 1] = av.y;
        As[lq + 2][2 * lr] = av.z; As[lq + 2][2 * lr + 1] = av.z;
        As[lq + 3][2 * lr] = av.w; As[lq + 3][2 * lr + 1] = av.w;
        *(float4*)&Bs[kb][jb] = bv;
        __syncthreads();
        #pragma unroll
        for (int kk = 0; kk < 16; kk++) {
            const ull* ap = (const ull*)&As[kk][ty * 8];
            const ull* bp = (const ull*)&Bs[kk][tx * 4];
            ull a[4], bb[2];
            #pragma unroll
            for (int r = 0; r < 4; r++) a[r] = ap[r];
            bb[0] = bp[0]; bb[1] = bp[1];
            #pragma unroll
            for (int r = 0; r < 4; r++) {
                acc[r][0] = ffma2(a[r], bb[0], acc[r][0]);
                acc[r][1] = ffma2(a[r], bb[1], acc[r][1]);
            }
        }
    }
}

// dual: z=0: P2 = P@P ; z=1: PS = P@SigmaN (one launch, runs concurrently)
__global__ void __launch_bounds__(256) k_ns_dual(int pb) {
    const float* P  = pb ? g_Pb : g_Pa;
    const float* Bm = blockIdx.z ? g_SigmaN : P;
    float*       Cm = blockIdx.z ? g_PS : g_P2;
    const int i0 = blockIdx.y * 64, j0 = blockIdx.x * 64;
    ull acc[4][2];
    mm512_acc(P, Bm, i0, j0, acc);
    const int tx = threadIdx.x & 15, ty = threadIdx.x >> 4;
    #pragma unroll
    for (int r = 0; r < 4; r++) {
        float* row = Cm + (size_t)(i0 + ty * 4 + r) * 512 + j0 + tx * 4;
        float2 v0 = u2f2(acc[r][0]), v1 = u2f2(acc[r][1]);
        row[0] = v0.x; row[1] = v0.y; row[2] = v1.x; row[3] = v1.y;
    }
}

// Pnext = 1.5*P - 0.5*(P2 @ PS)
__global__ void __launch_bounds__(256) k_ns_combine(int pb) {
    const float* Pc = pb ? g_Pb : g_Pa;
    float*       Pn = pb ? g_Pa : g_Pb;
    const int i0 = blockIdx.y * 64, j0 = blockIdx.x * 64;
    ull acc[4][2];
    mm512_acc(g_P2, g_PS, i0, j0, acc);
    const int tx = threadIdx.x & 15, ty = threadIdx.x >> 4;
    #pragma unroll
    for (int r = 0; r < 4; r++) {
        const size_t base = (size_t)(i0 + ty * 4 + r) * 512 + j0 + tx * 4;
        float2 v0 = u2f2(acc[r][0]), v1 = u2f2(acc[r][1]);
        Pn[base + 0] = 1.5f * Pc[base + 0] - 0.5f * v0.x;
        Pn[base + 1] = 1.5f * Pc[base + 1] - 0.5f * v0.y;
        Pn[base + 2] = 1.5f * Pc[base + 2] - 0.5f * v1.x;
        Pn[base + 3] = 1.5f * Pc[base + 3] - 0.5f * v1.y;
    }
}

// M = rot @ P_final * sqrt(1/tr)
__global__ void __launch_bounds__(256) k_rotP(const float* __restrict__ rot, int pb) {
    const float* Pf = pb ? g_Pb : g_Pa;
    const int i0 = blockIdx.y * 64, j0 = blockIdx.x * 64;
    ull acc[4][2];
    mm512_acc(rot, Pf, i0, j0, acc);
    const float s = g_scal[1];
    const int tx = threadIdx.x & 15, ty = threadIdx.x >> 4;
    #pragma unroll
    for (int r = 0; r < 4; r++) {
        float* row = g_M + (size_t)(i0 + ty * 4 + r) * 512 + j0 + tx * 4;
        float2 v0 = u2f2(acc[r][0]), v1 = u2f2(acc[r][1]);
        row[0] = v0.x * s; row[1] = v0.y * s; row[2] = v1.x * s; row[3] = v1.y * s;
    }
}

__global__ void k_bias() {
    const int i = blockIdx.x * 256 + threadIdx.x;
    float s = 0.f;
    #pragma unroll 8
    for (int c = 0; c < CH; c++) s += g_M[(size_t)i * CH + c] * g_mean[c];
    g_bias[i] = s;
}

// ---------------- out[b] = M @ X_b - bias (128x128 tiles) -------------------
__global__ void __launch_bounds__(256) k_out(const float* __restrict__ X,
                                             float* __restrict__ out) {
    const int b  = blockIdx.z;
    const int i0 = blockIdx.y * 128;
    const int s0 = blockIdx.x * 128;
    const float* Xb = X + (size_t)b * CH * SP;
    float* Ob = out + (size_t)b * CH * SP;

    __shared__ float As[8][256];
    __shared__ float Bs[8][128];

    const int tid = threadIdx.x;
    const int tx = tid & 15, ty = tid >> 4;

    ull acc[8][4];
    #pragma unroll
    for (int r = 0; r < 8; r++)
        #pragma unroll
        for (int c = 0; c < 4; c++) acc[r][c] = 0ull;

    const int lr = tid >> 1;          // M row 0..127
    const int lq = (tid & 1) * 4;     // M k 0/4
    const int kb = tid >> 5;          // X k row 0..7
    const int sb = (tid & 31) * 4;    // X col

    const bool bvalid = (s0 + sb) < SP;

    for (int k0 = 0; k0 < CH; k0 += 8) {
        float4 av = *(const float4*)(g_M + (size_t)(i0 + lr) * CH + k0 + lq);
        float4 bv = make_float4(0.f, 0.f, 0.f, 0.f);
        if (bvalid) bv = *(const float4*)(Xb + (size_t)(k0 + kb) * SP + s0 + sb);
        __syncthreads();
        As[lq + 0][2 * lr] = av.x; As[lq + 0][2 * lr + 1] = av.x;
        As[lq + 1][2 * lr] = av.y; As[lq + 1][2 * lr + 1] = av.y;
        As[lq + 2][2 * lr] = av.z; As[lq + 2][2 * lr + 1] = av.z;
        As[lq + 3][2 * lr] = av.w; As[lq + 3][2 * lr + 1] = av.w;
        *(float4*)&Bs[kb][sb] = bv;
        __syncthreads();
        #pragma unroll
        for (int kk = 0; kk < 8; kk++) {
            const ull* ap = (const ull*)&As[kk][ty * 16];
            const ull* bp = (const ull*)&Bs[kk][tx * 8];
            ull a[8], bb[4];
            #pragma unroll
            for (int r = 0; r < 8; r++) a[r] = ap[r];
            #pragma unroll
            for (int c = 0; c < 4; c++) bb[c] = bp[c];
            #pragma unroll
            for (int r = 0; r < 8; r++)
                #pragma unroll
                for (int c = 0; c < 4; c++)
                    acc[r][c] = ffma2(a[r], bb[c], acc[r][c]);
        }
    }

    const int sj = s0 + tx * 8;
    if (sj < SP) {
        #pragma unroll
        for (int r = 0; r < 8; r++) {
            const int gi = i0 + ty * 8 + r;
            const float bi = g_bias[gi];
            float* row = Ob + (size_t)gi * SP + sj;
            #pragma unroll
            for (int c = 0; c < 4; c++) {
                float2 v = u2f2(acc[r][c]);
                row[2 * c]     = v.x - bi;
                row[2 * c + 1] = v.y - bi;
            }
        }
    }
}

// ---------------- launch ----------------------------------------------------
extern "C" void kernel_launch(void* const* d_in, const int* in_sizes, int n_in,
                              void* d_out, int out_size) {
    const float* X   = (const float*)d_in[0];
    const float* rot = (const float*)d_in[1];
    float* out = (float*)d_out;
    (void)in_sizes; (void)n_in; (void)out_size;

    k_mean_part<<<dim3(CH, NB), 256>>>(X);
    k_mean_final<<<2, 256>>>();

    k_gram<<<dim3(4, 4, NB), 256>>>(X);
    k_sigma<<<1024, 256>>>();
    k_trace<<<1, 512>>>();
    k_prep<<<1024, 256>>>();

    // 10 Newton-Schulz iterations (T=10 fixed by setup_inputs)
    for (int t = 0; t < 10; t++) {
        const int pb = t & 1;                   // which buffer holds P_t
        k_ns_dual<<<dim3(8, 8, 2), 256>>>(pb);  // P2 = P@P, PS = P@SigmaN
        k_ns_combine<<<dim3(8, 8), 256>>>(pb);  // P_{t+1} = 1.5P - 0.5*P2@PS
    }
    // after 10 iters, P_final sits in g_Pa (even count)
    k_rotP<<<dim3(8, 8), 256>>>(rot, 0);
    k_bias<<<2, 256>>>();

    k_out<<<dim3(25, 4, NB), 256>>>(X, out);
}

// round 6
// speedup vs baseline: 2.2452x; 2.2440x over previous
#include <cuda_runtime.h>
#include <cuda_bf16.h>
#include <math.h>
#include <stdint.h>

#define CH   512
#define SP   3136
#define NB   32
#define MTOT 100352
#define EPSV 1e-5f

typedef unsigned long long ull;

// ===================== PTX helpers =========================================
__device__ __forceinline__ ull ffma2(ull a, ull b, ull c) {
    ull d;
    asm("fma.rn.f32x2 %0, %1, %2, %3;" : "=l"(d) : "l"(a), "l"(b), "l"(c));
    return d;
}
__device__ __forceinline__ float2 u2f2(ull v) {
    float2 r;
    asm("mov.b64 {%0, %1}, %2;" : "=f"(r.x), "=f"(r.y) : "l"(v));
    return r;
}
__device__ __forceinline__ uint32_t smem_u32(const void* p) {
    uint32_t a;
    asm("{ .reg .u64 t; cvta.to.shared.u64 t, %1; cvt.u32.u64 %0, t; }"
        : "=r"(a) : "l"(p));
    return a;
}
__device__ __forceinline__ void ldsm4(uint32_t r[4], uint32_t a) {
    asm volatile("ldmatrix.sync.aligned.m8n8.x4.shared.b16 {%0,%1,%2,%3}, [%4];"
                 : "=r"(r[0]), "=r"(r[1]), "=r"(r[2]), "=r"(r[3]) : "r"(a));
}
__device__ __forceinline__ void ldsm4t(uint32_t r[4], uint32_t a) {
    asm volatile("ldmatrix.sync.aligned.m8n8.x4.trans.shared.b16 {%0,%1,%2,%3}, [%4];"
                 : "=r"(r[0]), "=r"(r[1]), "=r"(r[2]), "=r"(r[3]) : "r"(a));
}
__device__ __forceinline__ void mma16816(float c[4], const uint32_t a[4],
                                         const uint32_t b[2]) {
    asm volatile("mma.sync.aligned.m16n8k16.row.col.f32.bf16.bf16.f32 "
                 "{%0,%1,%2,%3}, {%4,%5,%6,%7}, {%8,%9}, {%0,%1,%2,%3};"
                 : "+f"(c[0]), "+f"(c[1]), "+f"(c[2]), "+f"(c[3])
                 : "r"(a[0]), "r"(a[1]), "r"(a[2]), "r"(a[3]),
                   "r"(b[0]), "r"(b[1]));
}

// ===================== scratch globals =====================================
__device__ __align__(16) __nv_bfloat16 g_Xhi[(size_t)NB * CH * SP];
__device__ __align__(16) __nv_bfloat16 g_Xlo[(size_t)NB * CH * SP];
__device__ __align__(16) __nv_bfloat16 g_Mhi[CH * CH];
__device__ __align__(16) __nv_bfloat16 g_Mlo[CH * CH];
__device__ float g_meanpart[NB * CH];
__device__ float g_mean[CH];
__device__ __align__(16) float g_Gsl[(size_t)NB * CH * CH];   // 32 K-slices
__device__ float g_Sigma[CH * CH];
__device__ float g_SigmaN[CH * CH];
__device__ float g_Pa[CH * CH];
__device__ float g_Pb[CH * CH];
__device__ float g_P2[CH * CH];
__device__ float g_PS[CH * CH];
__device__ float g_M[CH * CH];
__device__ float g_bias[CH];
__device__ float g_scal[2];

// ===================== convert + mean ======================================
__global__ void __launch_bounds__(256) k_convert(const float* __restrict__ X) {
    const int c = blockIdx.x, b = blockIdx.y;
    const size_t base = ((size_t)b * CH + c) * SP;
    const float* src = X + base;
    float s = 0.f;
    for (int i = threadIdx.x * 4; i < SP; i += 1024) {
        float4 v = *(const float4*)(src + i);
        s += (v.x + v.y) + (v.z + v.w);
        __nv_bfloat16 h0 = __float2bfloat16(v.x), h1 = __float2bfloat16(v.y);
        __nv_bfloat16 h2 = __float2bfloat16(v.z), h3 = __float2bfloat16(v.w);
        __nv_bfloat162 hh0; hh0.x = h0; hh0.y = h1;
        __nv_bfloat162 hh1; hh1.x = h2; hh1.y = h3;
        __nv_bfloat162 ll0, ll1;
        ll0.x = __float2bfloat16(v.x - __bfloat162float(h0));
        ll0.y = __float2bfloat16(v.y - __bfloat162float(h1));
        ll1.x = __float2bfloat16(v.z - __bfloat162float(h2));
        ll1.y = __float2bfloat16(v.w - __bfloat162float(h3));
        *(__nv_bfloat162*)(g_Xhi + base + i)     = hh0;
        *(__nv_bfloat162*)(g_Xhi + base + i + 2) = hh1;
        *(__nv_bfloat162*)(g_Xlo + base + i)     = ll0;
        *(__nv_bfloat162*)(g_Xlo + base + i + 2) = ll1;
    }
    __shared__ float red[256];
    red[threadIdx.x] = s;
    __syncthreads();
    for (int o = 128; o > 0; o >>= 1) {
        if (threadIdx.x < o) red[threadIdx.x] += red[threadIdx.x + o];
        __syncthreads();
    }
    if (threadIdx.x == 0) g_meanpart[b * CH + c] = red[0];
}

__global__ void k_mean_final() {
    const int c = blockIdx.x * 256 + threadIdx.x;
    float s = 0.f;
    #pragma unroll
    for (int b = 0; b < NB; b++) s += g_meanpart[b * CH + c];
    g_mean[c] = s * (1.0f / MTOT);
}

// ===================== Gram via mma.sync ===================================
// stage: Ahi[128x40(80B)] Alo Bhi Blo; rows padded to 80B (conflict-free ldsm)
#define G_STG  40960
#define G_SMEM (2 * G_STG)

__global__ void __launch_bounds__(256) k_gram_mma() {
    extern __shared__ char smem[];
    const int tid = threadIdx.x, wid = tid >> 5, lane = tid & 31;
    const int pair = blockIdx.x, slice = blockIdx.y;   // slice = batch
    const int PI[10] = {0,0,0,0,1,1,1,2,2,3};
    const int PJ[10] = {0,1,2,3,1,2,3,2,3,3};
    const int m0 = PI[pair] * 128, n0 = PJ[pair] * 128;
    const int wm = (wid & 3) * 32, wn = (wid >> 2) * 64;
    const int lr = tid >> 2, lq = tid & 3;
    const uint32_t sbase = smem_u32(smem);

    // ldmatrix per-lane coordinates
    const int aRow = wm + ((lane >> 3) & 1) * 8 + (lane & 7);
    const int aCol = (lane >> 4) * 16;
    const int bRow = wn + (lane >> 4) * 8 + (lane & 7);
    const int bCol = ((lane >> 3) & 1) * 16;

    float acc[2][8][4];
    #pragma unroll
    for (int mt = 0; mt < 2; mt++)
        #pragma unroll
        for (int nt = 0; nt < 8; nt++)
            #pragma unroll
            for (int q = 0; q < 4; q++) acc[mt][nt][q] = 0.f;

    uint4 v[8];
    const size_t Bbase = (size_t)slice * CH * SP;

#define G_LD(kk) do {                                                         \
    const size_t rb = Bbase + (size_t)(kk) * 32 + lq * 8;                     \
    _Pragma("unroll")                                                         \
    for (int i = 0; i < 2; i++) {                                             \
        const int r = lr + i * 64;                                            \
        v[i*4+0] = *(const uint4*)(g_Xhi + rb + (size_t)(m0 + r) * SP);       \
        v[i*4+1] = *(const uint4*)(g_Xlo + rb + (size_t)(m0 + r) * SP);       \
        v[i*4+2] = *(const uint4*)(g_Xhi + rb + (size_t)(n0 + r) * SP);       \
        v[i*4+3] = *(const uint4*)(g_Xlo + rb + (size_t)(n0 + r) * SP);       \
    } } while (0)

#define G_ST(sg) do { char* _s = smem + (sg) * G_STG;                         \
    _Pragma("unroll")                                                         \
    for (int i = 0; i < 2; i++) {                                             \
        const int off = (lr + i * 64) * 80 + lq * 16;                         \
        *(uint4*)(_s + off)         = v[i*4+0];                               \
        *(uint4*)(_s + 10240 + off) = v[i*4+1];                               \
        *(uint4*)(_s + 20480 + off) = v[i*4+2];                               \
        *(uint4*)(_s + 30720 + off) = v[i*4+3];                               \
    } } while (0)

    G_LD(0); G_ST(0); __syncthreads();
    for (int kk = 0; kk < 98; kk++) {
        if (kk < 97) G_LD(kk + 1);
        const uint32_t sa = sbase + (kk & 1) * G_STG;
        #pragma unroll
        for (int k16 = 0; k16 < 2; k16++) {
            const int kb = k16 * 32;
            uint32_t ah[2][4], al[2][4], bh[4][4], bl[4][4];
            #pragma unroll
            for (int mt = 0; mt < 2; mt++) {
                const uint32_t ao = sa + (aRow + mt * 16) * 80 + kb + aCol;
                ldsm4(ah[mt], ao);
                ldsm4(al[mt], ao + 10240);
            }
            #pragma unroll
            for (int np = 0; np < 4; np++) {
                const uint32_t bo = sa + 20480 + (bRow + np * 16) * 80 + kb + bCol;
                ldsm4(bh[np], bo);
                ldsm4(bl[np], bo + 10240);
            }
            #pragma unroll
            for (int mt = 0; mt < 2; mt++)
                #pragma unroll
                for (int np = 0; np < 4; np++) {
                    mma16816(acc[mt][np*2],   ah[mt], &bh[np][0]);
                    mma16816(acc[mt][np*2+1], ah[mt], &bh[np][2]);
                    mma16816(acc[mt][np*2],   ah[mt], &bl[np][0]);
                    mma16816(acc[mt][np*2+1], ah[mt], &bl[np][2]);
                    mma16816(acc[mt][np*2],   al[mt], &bh[np][0]);
                    mma16816(acc[mt][np*2+1], al[mt], &bh[np][2]);
                }
        }
        __syncthreads();
        if (kk < 97) { G_ST((kk + 1) & 1); __syncthreads(); }
    }
#undef G_LD
#undef G_ST

    float* dst = g_Gsl + (size_t)slice * CH * CH;
    const int g4 = lane >> 2, t2 = (lane & 3) * 2;
    #pragma unroll
    for (int mt = 0; mt < 2; mt++)
        #pragma unroll
        for (int nt = 0; nt < 8; nt++) {
            const int row = m0 + wm + mt * 16 + g4;
            const int col = n0 + wn + nt * 8 + t2;
            float2 v0; v0.x = acc[mt][nt][0]; v0.y = acc[mt][nt][1];
            float2 v1; v1.x = acc[mt][nt][2]; v1.y = acc[mt][nt][3];
            *(float2*)(dst + (size_t)row * CH + col)       = v0;
            *(float2*)(dst + (size_t)(row + 8) * CH + col) = v1;
        }
}

// ===================== Sigma / trace / prep =================================
__global__ void k_sigma() {
    const int idx = blockIdx.x * 256 + threadIdx.x;
    const int i = idx >> 9, j = idx & 511;
    const size_t off = ((i >> 7) <= (j >> 7)) ? ((size_t)i * CH + j)
                                              : ((size_t)j * CH + i);
    float s = 0.f;
    #pragma unroll 8
    for (int p = 0; p < NB; p++) s += g_Gsl[(size_t)p * CH * CH + off];
    float v = s * (1.0f / MTOT) - g_mean[i] * g_mean[j];
    if (i == j) v += EPSV;
    g_Sigma[idx] = v;
}

__global__ void k_trace() {
    __shared__ float red[512];
    const int t = threadIdx.x;
    red[t] = g_Sigma[t * (CH + 1)];
    __syncthreads();
    for (int o = 256; o > 0; o >>= 1) {
        if (t < o) red[t] += red[t + o];
        __syncthreads();
    }
    if (t == 0) {
        float inv = 1.0f / red[0];
        g_scal[0] = inv;
        g_scal[1] = sqrtf(inv);
    }
}

__global__ void k_prep() {
    const int idx = blockIdx.x * 256 + threadIdx.x;
    g_SigmaN[idx] = g_Sigma[idx] * g_scal[0];
    const int i = idx >> 9, j = idx & 511;
    g_Pa[idx] = (i == j) ? 1.0f : 0.0f;
}

// ===================== Newton-Schulz (SIMT f32x2, known-good) ===============
__device__ __forceinline__ void mm512_acc(const float* __restrict__ A,
                                          const float* __restrict__ B,
                                          int i0, int j0, ull acc[4][2]) {
    __shared__ float As[16][128];
    __shared__ float Bs[16][64];
    const int tid = threadIdx.x;
    const int tx = tid & 15, ty = tid >> 4;
    #pragma unroll
    for (int r = 0; r < 4; r++) { acc[r][0] = 0ull; acc[r][1] = 0ull; }
    const int lr = tid >> 2, lq = (tid & 3) * 4;
    const int kb = tid >> 4, jb = (tid & 15) * 4;
    for (int k0 = 0; k0 < 512; k0 += 16) {
        float4 av = *(const float4*)(A + (size_t)(i0 + lr) * 512 + k0 + lq);
        float4 bv = *(const float4*)(B + (size_t)(k0 + kb) * 512 + j0 + jb);
        __syncthreads();
        As[lq + 0][2 * lr] = av.x; As[lq + 0][2 * lr + 1] = av.x;
        As[lq + 1][2 * lr] = av.y; As[lq + 1][2 * lr + 1] = av.y;
        As[lq + 2][2 * lr] = av.z; As[lq + 2][2 * lr + 1] = av.z;
        As[lq + 3][2 * lr] = av.w; As[lq + 3][2 * lr + 1] = av.w;
        *(float4*)&Bs[kb][jb] = bv;
        __syncthreads();
        #pragma unroll
        for (int kk = 0; kk < 16; kk++) {
            const ull* ap = (const ull*)&As[kk][ty * 8];
            const ull* bp = (const ull*)&Bs[kk][tx * 4];
            ull a[4], bb[2];
            #pragma unroll
            for (int r = 0; r < 4; r++) a[r] = ap[r];
            bb[0] = bp[0]; bb[1] = bp[1];
            #pragma unroll
            for (int r = 0; r < 4; r++) {
                acc[r][0] = ffma2(a[r], bb[0], acc[r][0]);
                acc[r][1] = ffma2(a[r], bb[1], acc[r][1]);
            }
        }
    }
}

__global__ void __launch_bounds__(256) k_ns_dual(int pb) {
    const float* P  = pb ? g_Pb : g_Pa;
    const float* Bm = blockIdx.z ? g_SigmaN : P;
    float*       Cm = blockIdx.z ? g_PS : g_P2;
    const int i0 = blockIdx.y * 64, j0 = blockIdx.x * 64;
    ull acc[4][2];
    mm512_acc(P, Bm, i0, j0, acc);
    const int tx = threadIdx.x & 15, ty = threadIdx.x >> 4;
    #pragma unroll
    for (int r = 0; r < 4; r++) {
        float* row = Cm + (size_t)(i0 + ty * 4 + r) * 512 + j0 + tx * 4;
        float2 v0 = u2f2(acc[r][0]), v1 = u2f2(acc[r][1]);
        row[0] = v0.x; row[1] = v0.y; row[2] = v1.x; row[3] = v1.y;
    }
}

__global__ void __launch_bounds__(256) k_ns_combine(int pb) {
    const float* Pc = pb ? g_Pb : g_Pa;
    float*       Pn = pb ? g_Pa : g_Pb;
    const int i0 = blockIdx.y * 64, j0 = blockIdx.x * 64;
    ull acc[4][2];
    mm512_acc(g_P2, g_PS, i0, j0, acc);
    const int tx = threadIdx.x & 15, ty = threadIdx.x >> 4;
    #pragma unroll
    for (int r = 0; r < 4; r++) {
        const size_t base = (size_t)(i0 + ty * 4 + r) * 512 + j0 + tx * 4;
        float2 v0 = u2f2(acc[r][0]), v1 = u2f2(acc[r][1]);
        Pn[base + 0] = 1.5f * Pc[base + 0] - 0.5f * v0.x;
        Pn[base + 1] = 1.5f * Pc[base + 1] - 0.5f * v0.y;
        Pn[base + 2] = 1.5f * Pc[base + 2] - 0.5f * v1.x;
        Pn[base + 3] = 1.5f * Pc[base + 3] - 0.5f * v1.y;
    }
}

__global__ void __launch_bounds__(256) k_rotP(const float* __restrict__ rot, int pb) {
    const float* Pf = pb ? g_Pb : g_Pa;
    const int i0 = blockIdx.y * 64, j0 = blockIdx.x * 64;
    ull acc[4][2];
    mm512_acc(rot, Pf, i0, j0, acc);
    const float s = g_scal[1];
    const int tx = threadIdx.x & 15, ty = threadIdx.x >> 4;
    #pragma unroll
    for (int r = 0; r < 4; r++) {
        float* row = g_M + (size_t)(i0 + ty * 4 + r) * 512 + j0 + tx * 4;
        float2 v0 = u2f2(acc[r][0]), v1 = u2f2(acc[r][1]);
        row[0] = v0.x * s; row[1] = v0.y * s; row[2] = v1.x * s; row[3] = v1.y * s;
    }
}

__global__ void k_Msplit() {
    const int idx = blockIdx.x * 256 + threadIdx.x;
    float v = g_M[idx];
    __nv_bfloat16 h = __float2bfloat16(v);
    g_Mhi[idx] = h;
    g_Mlo[idx] = __float2bfloat16(v - __bfloat162float(h));
}

__global__ void k_bias() {
    const int i = blockIdx.x * 256 + threadIdx.x;
    float s = 0.f;
    #pragma unroll 8
    for (int c = 0; c < CH; c++) s += g_M[(size_t)i * CH + c] * g_mean[c];
    g_bias[i] = s;
}

// ===================== out = M@X - bias via mma.sync ========================
// stage: Ahi[128x80B]=10240 Alo=10240 Bhi[32x256B]=8192 Blo=8192 => 36864
#define O_STG  36864
#define O_SMEM (2 * O_STG)

__global__ void __launch_bounds__(256) k_out_mma(float* __restrict__ out) {
    extern __shared__ char smem[];
    const int tid = threadIdx.x, wid = tid >> 5, lane = tid & 31;
    const int b = blockIdx.z;
    const int i0 = blockIdx.y * 128;
    const int s0 = blockIdx.x * 128;
    const int wm = (wid & 3) * 32, wn = (wid >> 2) * 64;
    const int lr = tid >> 2, lq = tid & 3;         // A loader
    const int br = tid >> 4, bg = tid & 15;        // B loader
    const uint32_t sbase = smem_u32(smem);

    const int aRow = wm + ((lane >> 3) & 1) * 8 + (lane & 7);
    const int aCol = (lane >> 4) * 16;
    const int bKr  = ((lane >> 3) & 1) * 8 + (lane & 7);   // + k16*16
    const int bGg  = (wn >> 3) + (lane >> 4);              // + np*2

    float acc[2][8][4];
    #pragma unroll
    for (int mt = 0; mt < 2; mt++)
        #pragma unroll
        for (int nt = 0; nt < 8; nt++)
            #pragma unroll
            for (int q = 0; q < 4; q++) acc[mt][nt][q] = 0.f;

    uint4 v[8];
    const size_t Xb = (size_t)b * CH * SP;
    const int scol = s0 + bg * 8;
    const bool sok = scol < SP;

#define O_LD(kk) do {                                                         \
    const int k0 = (kk) * 32;                                                 \
    _Pragma("unroll")                                                         \
    for (int i = 0; i < 2; i++) {                                             \
        const int r = lr + i * 64;                                            \
        v[i*4+0] = *(const uint4*)(g_Mhi + (size_t)(i0 + r) * CH + k0 + lq*8);\
        v[i*4+1] = *(const uint4*)(g_Mlo + (size_t)(i0 + r) * CH + k0 + lq*8);\
        const int kr = br + i * 16;                                           \
        if (sok) {                                                            \
            v[i*4+2] = *(const uint4*)(g_Xhi + Xb + (size_t)(k0+kr)*SP+scol); \
            v[i*4+3] = *(const uint4*)(g_Xlo + Xb + (size_t)(k0+kr)*SP+scol); \
        } else {                                                              \
            v[i*4+2] = make_uint4(0,0,0,0); v[i*4+3] = make_uint4(0,0,0,0);   \
        }                                                                     \
    } } while (0)

#define O_ST(sg) do { char* _s = smem + (sg) * O_STG;                         \
    _Pragma("unroll")                                                         \
    for (int i = 0; i < 2; i++) {                                             \
        const int offA = (lr + i * 64) * 80 + lq * 16;                        \
        *(uint4*)(_s + offA)         = v[i*4+0];                              \
        *(uint4*)(_s + 10240 + offA) = v[i*4+1];                              \
        const int kr = br + i * 16;                                           \
        const int offB = kr * 256 + ((bg ^ (kr & 7)) << 4);                   \
        *(uint4*)(_s + 20480 + offB) = v[i*4+2];                              \
        *(uint4*)(_s + 28672 + offB) = v[i*4+3];                              \
    } } while (0)

    O_LD(0); O_ST(0); __syncthreads();
    for (int kk = 0; kk < 16; kk++) {
        if (kk < 15) O_LD(kk + 1);
        const uint32_t sa = sbase + (kk & 1) * O_STG;
        #pragma unroll
        for (int k16 = 0; k16 < 2; k16++) {
            uint32_t ah[2][4], al[2][4], bh[4][4], bl[4][4];
            #pragma unroll
            for (int mt = 0; mt < 2; mt++) {
                const uint32_t ao = sa + (aRow + mt * 16) * 80 + k16 * 32 + aCol;
                ldsm4(ah[mt], ao);
                ldsm4(al[mt], ao + 10240);
            }
            const int kr = k16 * 16 + bKr;
            #pragma unroll
            for (int np = 0; np < 4; np++) {
                const uint32_t bo = sa + 20480 + kr * 256 +
                                    (((bGg + np * 2) ^ (kr & 7)) << 4);
                ldsm4t(bh[np], bo);
                ldsm4t(bl[np], bo + 8192);
            }
            #pragma unroll
            for (int mt = 0; mt < 2; mt++)
                #pragma unroll
                for (int np = 0; np < 4; np++) {
                    mma16816(acc[mt][np*2],   ah[mt], &bh[np][0]);
                    mma16816(acc[mt][np*2+1], ah[mt], &bh[np][2]);
                    mma16816(acc[mt][np*2],   ah[mt], &bl[np][0]);
                    mma16816(acc[mt][np*2+1], ah[mt], &bl[np][2]);
                    mma16816(acc[mt][np*2],   al[mt], &bh[np][0]);
                    mma16816(acc[mt][np*2+1], al[mt], &bh[np][2]);
                }
        }
        __syncthreads();
        if (kk < 15) { O_ST((kk + 1) & 1); __syncthreads(); }
    }
#undef O_LD
#undef O_ST

    const int g4 = lane >> 2, t2 = (lane & 3) * 2;
    float* Ob = out + Xb;
    #pragma unroll
    for (int mt = 0; mt < 2; mt++) {
        const int gi = i0 + wm + mt * 16 + g4;
        const float b0 = g_bias[gi], b1 = g_bias[gi + 8];
        #pragma unroll
        for (int nt = 0; nt < 8; nt++) {
            const int col = s0 + wn + nt * 8 + t2;
            if (col < SP) {
                float2 v0; v0.x = acc[mt][nt][0] - b0; v0.y = acc[mt][nt][1] - b0;
                float2 v1; v1.x = acc[mt][nt][2] - b1; v1.y = acc[mt][nt][3] - b1;
                *(float2*)(Ob + (size_t)gi * SP + col)       = v0;
                *(float2*)(Ob + (size_t)(gi + 8) * SP + col) = v1;
            }
        }
    }
}

// ===================== launch ==============================================
extern "C" void kernel_launch(void* const* d_in, const int* in_sizes, int n_in,
                              void* d_out, int out_size) {
    const float* X   = (const float*)d_in[0];
    const float* rot = (const float*)d_in[1];
    float* out = (float*)d_out;
    (void)in_sizes; (void)n_in; (void)out_size;

    static int attr_done = 0;
    if (!attr_done) {
        cudaFuncSetAttribute(k_gram_mma, cudaFuncAttributeMaxDynamicSharedMemorySize, G_SMEM);
        cudaFuncSetAttribute(k_out_mma,  cudaFuncAttributeMaxDynamicSharedMemorySize, O_SMEM);
        attr_done = 1;
    }

    k_convert<<<dim3(CH, NB), 256>>>(X);
    k_mean_final<<<2, 256>>>();

    k_gram_mma<<<dim3(10, NB), 256, G_SMEM>>>();
    k_sigma<<<1024, 256>>>();
    k_trace<<<1, 512>>>();
    k_prep<<<1024, 256>>>();

    for (int t = 0; t < 10; t++) {
        const int pb = t & 1;
        k_ns_dual<<<dim3(8, 8, 2), 256>>>(pb);
        k_ns_combine<<<dim3(8, 8), 256>>>(pb);
    }
    k_rotP<<<dim3(8, 8), 256>>>(rot, 0);
    k_Msplit<<<1024, 256>>>();
    k_bias<<<2, 256>>>();

    k_out_mma<<<dim3(25, 4, NB), 256, O_SMEM>>>(out);
}